// round 1
// baseline (speedup 1.0000x reference)
#include <cuda_runtime.h>
#include <math.h>

// ---------------- problem constants ----------------
#define NRR 20000
#define NCC 5000
#define ERR 320000
#define ECC 80000
#define DIN 6
#define HID 128
#define KNN 3
#define NEG 0.2f

// ---------------- static scratch (device globals; no allocation) ----------------
__device__ float g_hw_r[NRR * HID];     // h = x @ W (resting)
__device__ float g_h1_r[NRR * HID];     // layer-1 output (relu'd)
__device__ float g_h2_r[NRR * HID];     // layer-2 output (relu'd)
__device__ float g_hw_c[NCC * HID];
__device__ float g_h1_c[NCC * HID];
__device__ float g_h2_c[NCC * HID];
__device__ float g_es[NRR];             // e_src per node (reused per branch/layer)
__device__ float g_ed[NRR];             // e_dst per node
__device__ float g_mm[NRR];             // segment max
__device__ float g_dn[NRR];             // segment softmax denom
__device__ int   g_cnt_r[NRR];
__device__ int   g_cur_r[NRR];
__device__ int   g_rp_r[NRR + 1];
__device__ int   g_col_r[ERR + NRR];
__device__ int   g_cnt_c[NCC];
__device__ int   g_cur_c[NCC];
__device__ int   g_rp_c[NCC + 1];
__device__ int   g_col_c[ECC + NCC];
__device__ float g_nr2[NRR];            // ||h_r||^2
__device__ float g_nc2[NCC];            // ||h_c||^2
__device__ float g_d2[(size_t)NCC * NRR];   // 400 MB distance matrix
__device__ int   g_nn[NCC * KNN];
__device__ float g_pool[NRR * HID];
__device__ int   g_pcnt[NRR];

// ---------------- init / zero ----------------
__global__ void k_init() {
    int i = blockIdx.x * blockDim.x + threadIdx.x;
    int st = gridDim.x * blockDim.x;
    for (int t = i; t < NRR * HID; t += st) g_pool[t] = 0.f;
    for (int t = i; t < NRR; t += st) { g_cnt_r[t] = 1; g_cur_r[t] = 0; g_pcnt[t] = 0; }
    for (int t = i; t < NCC; t += st) { g_cnt_c[t] = 1; g_cur_c[t] = 0; }
}

// ---------------- CSR build ----------------
__global__ void k_count(const int* __restrict__ dst, int E, int* __restrict__ cnt) {
    int i = blockIdx.x * blockDim.x + threadIdx.x;
    if (i < E) atomicAdd(&cnt[dst[i]], 1);
}

__global__ void k_scan(const int* __restrict__ cnt, int* __restrict__ rp, int n) {
    __shared__ int part[1024];
    int t = threadIdx.x;
    int chunk = (n + 1023) / 1024;
    int beg = t * chunk;
    int end = min(n, beg + chunk);
    int s = 0;
    for (int i = beg; i < end; i++) s += cnt[i];
    part[t] = s;
    __syncthreads();
    for (int off = 1; off < 1024; off <<= 1) {
        int v = (t >= off) ? part[t - off] : 0;
        __syncthreads();
        part[t] += v;
        __syncthreads();
    }
    int run = part[t] - s;  // exclusive prefix
    for (int i = beg; i < end; i++) { rp[i] = run; run += cnt[i]; }
    if (t == 1023) rp[n] = part[1023];
}

__global__ void k_scatter(const int* __restrict__ src, const int* __restrict__ dst, int E,
                          const int* __restrict__ rp, int* __restrict__ cur,
                          int* __restrict__ colarr) {
    int i = blockIdx.x * blockDim.x + threadIdx.x;
    if (i < E) {
        int d = dst[i];
        int pos = rp[d] + atomicAdd(&cur[d], 1);
        colarr[pos] = src[i];
    }
}

__global__ void k_selfloop(const int* __restrict__ rp, int* __restrict__ colarr, int n) {
    int i = blockIdx.x * blockDim.x + threadIdx.x;
    if (i < n) colarr[rp[i + 1] - 1] = i;
}

// ---------------- GAT linear layers ----------------
// layer 1: h = x(n x 6) @ W(6 x 128), fused attention dots. one warp per node.
__global__ void k_lin1(const float* __restrict__ x, const float* __restrict__ W,
                       const float* __restrict__ as_, const float* __restrict__ ad_,
                       float* __restrict__ h, float* __restrict__ es, float* __restrict__ ed,
                       int n) {
    int w = (blockIdx.x * blockDim.x + threadIdx.x) >> 5;
    int lane = threadIdx.x & 31;
    if (w >= n) return;
    float xv[DIN];
#pragma unroll
    for (int k = 0; k < DIN; k++) xv[k] = x[w * DIN + k];
    float hv[4], ps = 0.f, pd = 0.f;
#pragma unroll
    for (int q = 0; q < 4; q++) {
        int j = lane * 4 + q;
        float a = 0.f;
#pragma unroll
        for (int k = 0; k < DIN; k++) a = fmaf(xv[k], W[k * HID + j], a);
        hv[q] = a;
        ps = fmaf(a, as_[j], ps);
        pd = fmaf(a, ad_[j], pd);
    }
    *(float4*)&h[(size_t)w * HID + lane * 4] = make_float4(hv[0], hv[1], hv[2], hv[3]);
#pragma unroll
    for (int o = 16; o > 0; o >>= 1) {
        ps += __shfl_xor_sync(0xffffffffu, ps, o);
        pd += __shfl_xor_sync(0xffffffffu, pd, o);
    }
    if (lane == 0) { es[w] = ps; ed[w] = pd; }
}

// layer 2 GEMM: C(M x 128) = A(M x 128) @ B(128 x 128). block = 64 rows x 128 cols.
__global__ void __launch_bounds__(256) k_gemm128(const float* __restrict__ A,
                                                 const float* __restrict__ B,
                                                 float* __restrict__ C, int M) {
    __shared__ float As[16][64];
    __shared__ float Bs[16][128];
    int tid = threadIdx.x;
    int tc = tid & 31;   // col group (4 cols)
    int tr = tid >> 5;   // row group (8 rows)
    int row0 = blockIdx.x * 64;
    float acc[8][4];
#pragma unroll
    for (int i = 0; i < 8; i++)
#pragma unroll
        for (int j = 0; j < 4; j++) acc[i][j] = 0.f;

    for (int k0 = 0; k0 < HID; k0 += 16) {
        int row_l = tid >> 2, quad = tid & 3;
        int gr = row0 + row_l;
        float4 av = make_float4(0.f, 0.f, 0.f, 0.f);
        if (gr < M) av = *(const float4*)&A[(size_t)gr * HID + k0 + quad * 4];
        As[quad * 4 + 0][row_l] = av.x;
        As[quad * 4 + 1][row_l] = av.y;
        As[quad * 4 + 2][row_l] = av.z;
        As[quad * 4 + 3][row_l] = av.w;
        int kk = tid >> 4, cp = tid & 15;
        float4 bv0 = *(const float4*)&B[(size_t)(k0 + kk) * HID + cp * 8];
        float4 bv1 = *(const float4*)&B[(size_t)(k0 + kk) * HID + cp * 8 + 4];
        *(float4*)&Bs[kk][cp * 8] = bv0;
        *(float4*)&Bs[kk][cp * 8 + 4] = bv1;
        __syncthreads();
#pragma unroll
        for (int k2 = 0; k2 < 16; k2++) {
            float4 a0 = *(float4*)&As[k2][tr * 8];
            float4 a1 = *(float4*)&As[k2][tr * 8 + 4];
            float4 bb = *(float4*)&Bs[k2][tc * 4];
            float a[8] = {a0.x, a0.y, a0.z, a0.w, a1.x, a1.y, a1.z, a1.w};
            float b[4] = {bb.x, bb.y, bb.z, bb.w};
#pragma unroll
            for (int i = 0; i < 8; i++)
#pragma unroll
                for (int j = 0; j < 4; j++) acc[i][j] = fmaf(a[i], b[j], acc[i][j]);
        }
        __syncthreads();
    }
#pragma unroll
    for (int i = 0; i < 8; i++) {
        int r = row0 + tr * 8 + i;
        if (r < M)
            *(float4*)&C[(size_t)r * HID + tc * 4] =
                make_float4(acc[i][0], acc[i][1], acc[i][2], acc[i][3]);
    }
}

// attention dots for layer 2: es = h . a_src, ed = h . a_dst. warp per node.
__global__ void k_dots(const float* __restrict__ h, const float* __restrict__ as_,
                       const float* __restrict__ ad_, float* __restrict__ es,
                       float* __restrict__ ed, int n) {
    int w = (blockIdx.x * blockDim.x + threadIdx.x) >> 5;
    int lane = threadIdx.x & 31;
    if (w >= n) return;
    const float* hr = &h[(size_t)w * HID];
    float ps = 0.f, pd = 0.f;
#pragma unroll
    for (int t = 0; t < 4; t++) {
        int j = lane + 32 * t;
        float v = hr[j];
        ps = fmaf(v, as_[j], ps);
        pd = fmaf(v, ad_[j], pd);
    }
#pragma unroll
    for (int o = 16; o > 0; o >>= 1) {
        ps += __shfl_xor_sync(0xffffffffu, ps, o);
        pd += __shfl_xor_sync(0xffffffffu, pd, o);
    }
    if (lane == 0) { es[w] = ps; ed[w] = pd; }
}

// ---------------- segment softmax stats (online max+sum). warp per dst node. ----------------
__global__ void k_stats(const int* __restrict__ rp, const int* __restrict__ col,
                        const float* __restrict__ es, const float* __restrict__ edv,
                        float* __restrict__ mv, float* __restrict__ dnv, int n) {
    int w = (blockIdx.x * blockDim.x + threadIdx.x) >> 5;
    int lane = threadIdx.x & 31;
    if (w >= n) return;
    int beg = rp[w], end = rp[w + 1];
    float ed = edv[w];
    float m = -1e30f, s = 0.f;
    for (int idx = beg + lane; idx < end; idx += 32) {
        float e = es[col[idx]] + ed;
        e = e > 0.f ? e : NEG * e;
        float mn = fmaxf(m, e);
        s = s * __expf(m - mn) + __expf(e - mn);
        m = mn;
    }
#pragma unroll
    for (int o = 16; o > 0; o >>= 1) {
        float m2 = __shfl_xor_sync(0xffffffffu, m, o);
        float s2 = __shfl_xor_sync(0xffffffffu, s, o);
        float mn = fmaxf(m, m2);
        s = s * __expf(m - mn) + s2 * __expf(m2 - mn);
        m = mn;
    }
    if (lane == 0) { mv[w] = m; dnv[w] = s; }
}

// ---------------- attention-weighted aggregation + bias + relu. warp per dst node. ----------------
__global__ void k_agg(const int* __restrict__ rp, const int* __restrict__ col,
                      const float* __restrict__ hW, const float* __restrict__ es,
                      const float* __restrict__ edv, const float* __restrict__ mv,
                      const float* __restrict__ dnv, const float* __restrict__ bias,
                      float* __restrict__ out, int n) {
    int w = (blockIdx.x * blockDim.x + threadIdx.x) >> 5;
    int lane = threadIdx.x & 31;
    if (w >= n) return;
    int beg = rp[w], end = rp[w + 1];
    float ed = edv[w], md = mv[w];
    float inv = 1.f / fmaxf(dnv[w], 1e-16f);
    float a0 = 0.f, a1 = 0.f, a2 = 0.f, a3 = 0.f;
    for (int idx = beg; idx < end; idx++) {
        int s = col[idx];
        float e = es[s] + ed;
        e = e > 0.f ? e : NEG * e;
        float wgt = __expf(e - md) * inv;
        const float* hr = &hW[(size_t)s * HID];
        a0 = fmaf(wgt, hr[lane], a0);
        a1 = fmaf(wgt, hr[lane + 32], a1);
        a2 = fmaf(wgt, hr[lane + 64], a2);
        a3 = fmaf(wgt, hr[lane + 96], a3);
    }
    out[(size_t)w * HID + lane]      = fmaxf(a0 + bias[lane], 0.f);
    out[(size_t)w * HID + lane + 32] = fmaxf(a1 + bias[lane + 32], 0.f);
    out[(size_t)w * HID + lane + 64] = fmaxf(a2 + bias[lane + 64], 0.f);
    out[(size_t)w * HID + lane + 96] = fmaxf(a3 + bias[lane + 96], 0.f);
}

// ---------------- row norms ----------------
__global__ void k_norm(const float* __restrict__ h, float* __restrict__ nrm, int n) {
    int w = (blockIdx.x * blockDim.x + threadIdx.x) >> 5;
    int lane = threadIdx.x & 31;
    if (w >= n) return;
    const float* hr = &h[(size_t)w * HID];
    float s = 0.f;
#pragma unroll
    for (int t = 0; t < 4; t++) { float v = hr[lane + 32 * t]; s = fmaf(v, v, s); }
#pragma unroll
    for (int o = 16; o > 0; o >>= 1) s += __shfl_xor_sync(0xffffffffu, s, o);
    if (lane == 0) nrm[w] = s;
}

// ---------------- KNN distance GEMM: d2[c][r] = nc+nr-2*dot. 128x128 tile, 8x8/thread. ----------------
__global__ void __launch_bounds__(256) k_knn(const float* __restrict__ A,   // h2_c [NCC x 128]
                                             const float* __restrict__ B) { // h2_r [NRR x 128]
    __shared__ float As[16][128];
    __shared__ float Bs[16][128];
    int tid = threadIdx.x;
    int tx = tid & 15, ty = tid >> 4;
    int rb = blockIdx.x * 128;  // resting (N) tile
    int cb = blockIdx.y * 128;  // collider (M) tile
    float acc[8][8];
#pragma unroll
    for (int i = 0; i < 8; i++)
#pragma unroll
        for (int j = 0; j < 8; j++) acc[i][j] = 0.f;

    int rl = tid >> 1, kq = tid & 1;
    for (int k0 = 0; k0 < HID; k0 += 16) {
        {
            int gc = cb + rl;
            float4 v0 = make_float4(0.f, 0.f, 0.f, 0.f), v1 = v0;
            if (gc < NCC) {
                v0 = *(const float4*)&A[(size_t)gc * HID + k0 + kq * 8];
                v1 = *(const float4*)&A[(size_t)gc * HID + k0 + kq * 8 + 4];
            }
            As[kq * 8 + 0][rl] = v0.x; As[kq * 8 + 1][rl] = v0.y;
            As[kq * 8 + 2][rl] = v0.z; As[kq * 8 + 3][rl] = v0.w;
            As[kq * 8 + 4][rl] = v1.x; As[kq * 8 + 5][rl] = v1.y;
            As[kq * 8 + 6][rl] = v1.z; As[kq * 8 + 7][rl] = v1.w;
        }
        {
            int gr = rb + rl;
            float4 v0 = make_float4(0.f, 0.f, 0.f, 0.f), v1 = v0;
            if (gr < NRR) {
                v0 = *(const float4*)&B[(size_t)gr * HID + k0 + kq * 8];
                v1 = *(const float4*)&B[(size_t)gr * HID + k0 + kq * 8 + 4];
            }
            Bs[kq * 8 + 0][rl] = v0.x; Bs[kq * 8 + 1][rl] = v0.y;
            Bs[kq * 8 + 2][rl] = v0.z; Bs[kq * 8 + 3][rl] = v0.w;
            Bs[kq * 8 + 4][rl] = v1.x; Bs[kq * 8 + 5][rl] = v1.y;
            Bs[kq * 8 + 6][rl] = v1.z; Bs[kq * 8 + 7][rl] = v1.w;
        }
        __syncthreads();
#pragma unroll
        for (int kk = 0; kk < 16; kk++) {
            float4 t0 = *(float4*)&As[kk][ty * 8];
            float4 t1 = *(float4*)&As[kk][ty * 8 + 4];
            float4 u0 = *(float4*)&Bs[kk][tx * 8];
            float4 u1 = *(float4*)&Bs[kk][tx * 8 + 4];
            float a[8] = {t0.x, t0.y, t0.z, t0.w, t1.x, t1.y, t1.z, t1.w};
            float b[8] = {u0.x, u0.y, u0.z, u0.w, u1.x, u1.y, u1.z, u1.w};
#pragma unroll
            for (int i = 0; i < 8; i++)
#pragma unroll
                for (int j = 0; j < 8; j++) acc[i][j] = fmaf(a[i], b[j], acc[i][j]);
        }
        __syncthreads();
    }
#pragma unroll
    for (int i = 0; i < 8; i++) {
        int c = cb + ty * 8 + i;
        if (c < NCC) {
            float ncv = g_nc2[c];
            float* drow = &g_d2[(size_t)c * NRR];
            int r0 = rb + tx * 8;
            if (r0 + 7 < NRR) {
                float4 o0, o1;
                o0.x = ncv + g_nr2[r0 + 0] - 2.f * acc[i][0];
                o0.y = ncv + g_nr2[r0 + 1] - 2.f * acc[i][1];
                o0.z = ncv + g_nr2[r0 + 2] - 2.f * acc[i][2];
                o0.w = ncv + g_nr2[r0 + 3] - 2.f * acc[i][3];
                o1.x = ncv + g_nr2[r0 + 4] - 2.f * acc[i][4];
                o1.y = ncv + g_nr2[r0 + 5] - 2.f * acc[i][5];
                o1.z = ncv + g_nr2[r0 + 6] - 2.f * acc[i][6];
                o1.w = ncv + g_nr2[r0 + 7] - 2.f * acc[i][7];
                *(float4*)&drow[r0] = o0;
                *(float4*)&drow[r0 + 4] = o1;
            } else {
                for (int j = 0; j < 8; j++) {
                    int r = r0 + j;
                    if (r < NRR) drow[r] = ncv + g_nr2[r] - 2.f * acc[i][j];
                }
            }
        }
    }
}

// ---------------- top-3 per collider row (ties -> lower index, matching lax.top_k) ----------------
__device__ __forceinline__ bool d2_less(float v1, int i1, float v2, int i2) {
    return (v1 < v2) || (v1 == v2 && i1 < i2);
}

__global__ void k_top3() {
    int c = blockIdx.x;
    const float* row = &g_d2[(size_t)c * NRR];
    float bv0 = 1e30f, bv1 = 1e30f, bv2 = 1e30f;
    int bi0 = 0x7fffffff, bi1 = 0x7fffffff, bi2 = 0x7fffffff;
    for (int r = threadIdx.x; r < NRR; r += 256) {
        float v = row[r];
        if (d2_less(v, r, bv2, bi2)) {
            bv2 = v; bi2 = r;
            if (d2_less(bv2, bi2, bv1, bi1)) {
                float tv = bv1; int ti = bi1; bv1 = bv2; bi1 = bi2; bv2 = tv; bi2 = ti;
            }
            if (d2_less(bv1, bi1, bv0, bi0)) {
                float tv = bv0; int ti = bi0; bv0 = bv1; bi0 = bi1; bv1 = tv; bi1 = ti;
            }
        }
    }
    __shared__ float sv[768];
    __shared__ int si[768];
    sv[threadIdx.x * 3 + 0] = bv0; si[threadIdx.x * 3 + 0] = bi0;
    sv[threadIdx.x * 3 + 1] = bv1; si[threadIdx.x * 3 + 1] = bi1;
    sv[threadIdx.x * 3 + 2] = bv2; si[threadIdx.x * 3 + 2] = bi2;
    __syncthreads();
    if (threadIdx.x == 0) {
        float f0 = 1e30f, f1 = 1e30f, f2 = 1e30f;
        int j0 = 0x7fffffff, j1 = 0x7fffffff, j2 = 0x7fffffff;
        for (int t = 0; t < 768; t++) {
            float v = sv[t];
            int r = si[t];
            if (r == 0x7fffffff) continue;
            if (d2_less(v, r, f2, j2)) {
                f2 = v; j2 = r;
                if (d2_less(f2, j2, f1, j1)) {
                    float tv = f1; int ti = j1; f1 = f2; j1 = j2; f2 = tv; j2 = ti;
                }
                if (d2_less(f1, j1, f0, j0)) {
                    float tv = f0; int ti = j0; f0 = f1; j0 = j1; f1 = tv; j1 = ti;
                }
            }
        }
        g_nn[c * 3 + 0] = j0;
        g_nn[c * 3 + 1] = j1;
        g_nn[c * 3 + 2] = j2;
    }
}

// ---------------- scatter-mean pooling of collider features onto resting nodes ----------------
__global__ void k_pool(const float* __restrict__ hc) {
    int w = (blockIdx.x * blockDim.x + threadIdx.x) >> 5;
    int lane = threadIdx.x & 31;
    if (w >= NCC) return;
    const float* hr = &hc[(size_t)w * HID];
    float v0 = hr[lane], v1 = hr[lane + 32], v2 = hr[lane + 64], v3 = hr[lane + 96];
#pragma unroll
    for (int k = 0; k < KNN; k++) {
        int nn = g_nn[w * 3 + k];
        atomicAdd(&g_pool[(size_t)nn * HID + lane], v0);
        atomicAdd(&g_pool[(size_t)nn * HID + lane + 32], v1);
        atomicAdd(&g_pool[(size_t)nn * HID + lane + 64], v2);
        atomicAdd(&g_pool[(size_t)nn * HID + lane + 96], v3);
        if (lane == 0) atomicAdd(&g_pcnt[nn], 1);
    }
}

// ---------------- decoder: out = [h_r, pooled] @ W_dec + b_dec. warp per resting node. ----------------
__global__ void k_dec(const float* __restrict__ hr, const float* __restrict__ Wd,
                      const float* __restrict__ bd, float* __restrict__ out) {
    int w = (blockIdx.x * blockDim.x + threadIdx.x) >> 5;
    int lane = threadIdx.x & 31;
    if (w >= NRR) return;
    float inv = 1.f / fmaxf((float)g_pcnt[w], 1.f);
    float a0 = 0.f, a1 = 0.f, a2 = 0.f;
#pragma unroll
    for (int t = 0; t < 4; t++) {
        int j = lane + 32 * t;
        float hv = hr[(size_t)w * HID + j];
        float pv = g_pool[(size_t)w * HID + j] * inv;
        a0 = fmaf(hv, Wd[j * 3 + 0], a0); a0 = fmaf(pv, Wd[(HID + j) * 3 + 0], a0);
        a1 = fmaf(hv, Wd[j * 3 + 1], a1); a1 = fmaf(pv, Wd[(HID + j) * 3 + 1], a1);
        a2 = fmaf(hv, Wd[j * 3 + 2], a2); a2 = fmaf(pv, Wd[(HID + j) * 3 + 2], a2);
    }
#pragma unroll
    for (int o = 16; o > 0; o >>= 1) {
        a0 += __shfl_xor_sync(0xffffffffu, a0, o);
        a1 += __shfl_xor_sync(0xffffffffu, a1, o);
        a2 += __shfl_xor_sync(0xffffffffu, a2, o);
    }
    if (lane == 0) {
        out[w * 3 + 0] = a0 + bd[0];
        out[w * 3 + 1] = a1 + bd[1];
        out[w * 3 + 2] = a2 + bd[2];
    }
}

// ---------------- host launcher ----------------
extern "C" void kernel_launch(void* const* d_in, const int* in_sizes, int n_in,
                              void* d_out, int out_size) {
    const float* x_r  = (const float*)d_in[0];
    const float* x_c  = (const float*)d_in[1];
    const int*   ei_r = (const int*)d_in[2];
    const int*   ei_c = (const int*)d_in[3];
    // d_in[4] = knn_k (compile-time 3)
    const float* W_r1  = (const float*)d_in[5];
    const float* as_r1 = (const float*)d_in[6];
    const float* ad_r1 = (const float*)d_in[7];
    const float* b_r1  = (const float*)d_in[8];
    const float* W_r2  = (const float*)d_in[9];
    const float* as_r2 = (const float*)d_in[10];
    const float* ad_r2 = (const float*)d_in[11];
    const float* b_r2  = (const float*)d_in[12];
    const float* W_c1  = (const float*)d_in[13];
    const float* as_c1 = (const float*)d_in[14];
    const float* ad_c1 = (const float*)d_in[15];
    const float* b_c1  = (const float*)d_in[16];
    const float* W_c2  = (const float*)d_in[17];
    const float* as_c2 = (const float*)d_in[18];
    const float* ad_c2 = (const float*)d_in[19];
    const float* b_c2  = (const float*)d_in[20];
    const float* W_dec = (const float*)d_in[21];
    const float* b_dec = (const float*)d_in[22];
    float* out = (float*)d_out;

    // device-global scratch addresses (query only; no allocation)
    float *hw_r, *h1_r, *h2_r, *hw_c, *h1_c, *h2_c, *es, *ed, *mv, *dn, *nr2, *nc2;
    int *cnt_r, *cur_r, *rp_r, *col_r, *cnt_c, *cur_c, *rp_c, *col_c;
    cudaGetSymbolAddress((void**)&hw_r, g_hw_r);
    cudaGetSymbolAddress((void**)&h1_r, g_h1_r);
    cudaGetSymbolAddress((void**)&h2_r, g_h2_r);
    cudaGetSymbolAddress((void**)&hw_c, g_hw_c);
    cudaGetSymbolAddress((void**)&h1_c, g_h1_c);
    cudaGetSymbolAddress((void**)&h2_c, g_h2_c);
    cudaGetSymbolAddress((void**)&es, g_es);
    cudaGetSymbolAddress((void**)&ed, g_ed);
    cudaGetSymbolAddress((void**)&mv, g_mm);
    cudaGetSymbolAddress((void**)&dn, g_dn);
    cudaGetSymbolAddress((void**)&nr2, g_nr2);
    cudaGetSymbolAddress((void**)&nc2, g_nc2);
    cudaGetSymbolAddress((void**)&cnt_r, g_cnt_r);
    cudaGetSymbolAddress((void**)&cur_r, g_cur_r);
    cudaGetSymbolAddress((void**)&rp_r, g_rp_r);
    cudaGetSymbolAddress((void**)&col_r, g_col_r);
    cudaGetSymbolAddress((void**)&cnt_c, g_cnt_c);
    cudaGetSymbolAddress((void**)&cur_c, g_cur_c);
    cudaGetSymbolAddress((void**)&rp_c, g_rp_c);
    cudaGetSymbolAddress((void**)&col_c, g_col_c);

    // init scratch
    k_init<<<1024, 256>>>();

    // CSR build (both branches)
    k_count<<<(ERR + 255) / 256, 256>>>(ei_r + ERR, ERR, cnt_r);
    k_count<<<(ECC + 255) / 256, 256>>>(ei_c + ECC, ECC, cnt_c);
    k_scan<<<1, 1024>>>(cnt_r, rp_r, NRR);
    k_scan<<<1, 1024>>>(cnt_c, rp_c, NCC);
    k_scatter<<<(ERR + 255) / 256, 256>>>(ei_r, ei_r + ERR, ERR, rp_r, cur_r, col_r);
    k_scatter<<<(ECC + 255) / 256, 256>>>(ei_c, ei_c + ECC, ECC, rp_c, cur_c, col_c);
    k_selfloop<<<(NRR + 255) / 256, 256>>>(rp_r, col_r, NRR);
    k_selfloop<<<(NCC + 255) / 256, 256>>>(rp_c, col_c, NCC);

    const int WGR = (NRR + 7) / 8;  // warp-per-node grids
    const int WGC = (NCC + 7) / 8;

    // -------- resting branch --------
    k_lin1<<<WGR, 256>>>(x_r, W_r1, as_r1, ad_r1, hw_r, es, ed, NRR);
    k_stats<<<WGR, 256>>>(rp_r, col_r, es, ed, mv, dn, NRR);
    k_agg<<<WGR, 256>>>(rp_r, col_r, hw_r, es, ed, mv, dn, b_r1, h1_r, NRR);
    k_gemm128<<<(NRR + 63) / 64, 256>>>(h1_r, W_r2, hw_r, NRR);
    k_dots<<<WGR, 256>>>(hw_r, as_r2, ad_r2, es, ed, NRR);
    k_stats<<<WGR, 256>>>(rp_r, col_r, es, ed, mv, dn, NRR);
    k_agg<<<WGR, 256>>>(rp_r, col_r, hw_r, es, ed, mv, dn, b_r2, h2_r, NRR);

    // -------- collider branch --------
    k_lin1<<<WGC, 256>>>(x_c, W_c1, as_c1, ad_c1, hw_c, es, ed, NCC);
    k_stats<<<WGC, 256>>>(rp_c, col_c, es, ed, mv, dn, NCC);
    k_agg<<<WGC, 256>>>(rp_c, col_c, hw_c, es, ed, mv, dn, b_c1, h1_c, NCC);
    k_gemm128<<<(NCC + 63) / 64, 256>>>(h1_c, W_c2, hw_c, NCC);
    k_dots<<<WGC, 256>>>(hw_c, as_c2, ad_c2, es, ed, NCC);
    k_stats<<<WGC, 256>>>(rp_c, col_c, es, ed, mv, dn, NCC);
    k_agg<<<WGC, 256>>>(rp_c, col_c, hw_c, es, ed, mv, dn, b_c2, h2_c, NCC);

    // -------- KNN + pooling + decode --------
    k_norm<<<WGR, 256>>>(h2_r, nr2, NRR);
    k_norm<<<WGC, 256>>>(h2_c, nc2, NCC);
    dim3 kg((NRR + 127) / 128, (NCC + 127) / 128);
    k_knn<<<kg, 256>>>(h2_c, h2_r);
    k_top3<<<NCC, 256>>>();
    k_pool<<<WGC, 256>>>(h2_c);
    k_dec<<<WGR, 256>>>(h2_r, W_dec, b_dec, out);
}